// round 3
// baseline (speedup 1.0000x reference)
#include <cuda_runtime.h>

#define BATCH 16
#define NN 1024
#define FF 128

// Scratch (device globals: no allocation allowed in kernel_launch)
__device__ float g_dinv[BATCH * NN];            // 64 KB
__device__ float g_Xs[BATCH * NN * FF];         // 8 MB  (d[m] * X[m,f])
__device__ float g_Y[BATCH * NN * FF];          // 8 MB  (d[n]*((A@Xs)+Xs))

// ---------------------------------------------------------------------------
// Kernel 1: row degree -> d_inv_sqrt.  One warp per row of A (1024 floats).
// ---------------------------------------------------------------------------
__global__ void deg_kernel(const float* __restrict__ A) {
    int warp = (blockIdx.x * blockDim.x + threadIdx.x) >> 5;
    int lane = threadIdx.x & 31;
    if (warp >= BATCH * NN) return;
    const float4* row = (const float4*)(A + (size_t)warp * NN);
    float s = 0.f;
#pragma unroll
    for (int i = 0; i < 8; i++) {
        float4 v = row[lane + 32 * i];
        s += v.x + v.y + v.z + v.w;
    }
#pragma unroll
    for (int o = 16; o; o >>= 1) s += __shfl_xor_sync(0xffffffffu, s, o);
    if (lane == 0) g_dinv[warp] = rsqrtf(s + 1.0f);  // deg = sum(A) + 1 (identity)
}

// ---------------------------------------------------------------------------
// Kernel 2: Xs[b,m,f] = d[b,m] * X[b,m,f]   (vectorized float4)
// ---------------------------------------------------------------------------
__global__ void scale_kernel(const float* __restrict__ X) {
    int idx = blockIdx.x * blockDim.x + threadIdx.x;
    if (idx >= BATCH * NN * FF / 4) return;
    float4 v = ((const float4*)X)[idx];
    float d = g_dinv[idx / (FF / 4)];
    v.x *= d; v.y *= d; v.z *= d; v.w *= d;
    ((float4*)g_Xs)[idx] = v;
}

// ---------------------------------------------------------------------------
// Kernel 3: per batch b:  Y = d[n] * (A[b] @ Xs[b] + Xs[b])
// 128x128 output tile per block (full F width), KT=16, 8x8 per thread.
// ---------------------------------------------------------------------------
__global__ void __launch_bounds__(256) bmm_kernel(const float* __restrict__ A) {
    __shared__ float As[16][132];   // [k][m], +4 pad
    __shared__ float Bs[16][128];   // [k][f]
    int b = blockIdx.y;
    int m0 = blockIdx.x * 128;
    const float* Ab = A + (size_t)b * NN * NN;
    const float* Xb = g_Xs + (size_t)b * NN * FF;
    int tid = threadIdx.x;
    int tx = tid & 15, ty = tid >> 4;

    float acc[8][8] = {};

    for (int k0 = 0; k0 < NN; k0 += 16) {
        // A tile: rows m0..m0+127, cols k0..k0+15  (transpose into As[k][m])
#pragma unroll
        for (int i = 0; i < 2; i++) {
            int t = tid + 256 * i;          // 0..511
            int m = t >> 2;                 // 0..127
            int kq = (t & 3) * 4;           // 0,4,8,12
            float4 v = *(const float4*)(Ab + (size_t)(m0 + m) * NN + k0 + kq);
            As[kq + 0][m] = v.x;
            As[kq + 1][m] = v.y;
            As[kq + 2][m] = v.z;
            As[kq + 3][m] = v.w;
        }
        // B tile: Xs rows k0..k0+15, all 128 cols
#pragma unroll
        for (int i = 0; i < 2; i++) {
            int t = tid + 256 * i;
            int k = t >> 5;                 // 0..15
            int f = (t & 31) * 4;
            *(float4*)&Bs[k][f] = *(const float4*)(Xb + (size_t)(k0 + k) * FF + f);
        }
        __syncthreads();
#pragma unroll
        for (int kk = 0; kk < 16; kk++) {
            float4 a0 = *(const float4*)&As[kk][ty * 8];
            float4 a1 = *(const float4*)&As[kk][ty * 8 + 4];
            float4 b0 = *(const float4*)&Bs[kk][tx * 8];
            float4 b1 = *(const float4*)&Bs[kk][tx * 8 + 4];
            float ar[8] = {a0.x, a0.y, a0.z, a0.w, a1.x, a1.y, a1.z, a1.w};
            float br[8] = {b0.x, b0.y, b0.z, b0.w, b1.x, b1.y, b1.z, b1.w};
#pragma unroll
            for (int i = 0; i < 8; i++)
#pragma unroll
                for (int j = 0; j < 8; j++)
                    acc[i][j] += ar[i] * br[j];
        }
        __syncthreads();
    }

    // Epilogue: Y[n,f] = d[n] * (acc + Xs[n,f])   (identity term + row scale)
#pragma unroll
    for (int i = 0; i < 8; i++) {
        int n = m0 + ty * 8 + i;
        float d = g_dinv[b * NN + n];
        float* yrow = g_Y + (size_t)b * NN * FF + (size_t)n * FF;
        const float* xrow = Xb + (size_t)n * FF;
#pragma unroll
        for (int j = 0; j < 8; j += 4) {
            int f = tx * 8 + j;
            float4 xs = *(const float4*)(xrow + f);
            float4 o;
            o.x = d * (acc[i][j + 0] + xs.x);
            o.y = d * (acc[i][j + 1] + xs.y);
            o.z = d * (acc[i][j + 2] + xs.z);
            o.w = d * (acc[i][j + 3] + xs.w);
            *(float4*)(yrow + f) = o;
        }
    }
}

// ---------------------------------------------------------------------------
// Kernel 4: out[b] = Y[b] @ W     (1024x128 @ 128x128, K=128)
// ---------------------------------------------------------------------------
__global__ void __launch_bounds__(256) wmul_kernel(const float* __restrict__ W,
                                                   float* __restrict__ out) {
    __shared__ float As[16][132];
    __shared__ float Bs[16][128];
    int b = blockIdx.y;
    int m0 = blockIdx.x * 128;
    const float* Yb = g_Y + (size_t)b * NN * FF;
    int tid = threadIdx.x;
    int tx = tid & 15, ty = tid >> 4;

    float acc[8][8] = {};

    for (int k0 = 0; k0 < FF; k0 += 16) {
#pragma unroll
        for (int i = 0; i < 2; i++) {
            int t = tid + 256 * i;
            int m = t >> 2;
            int kq = (t & 3) * 4;
            float4 v = *(const float4*)(Yb + (size_t)(m0 + m) * FF + k0 + kq);
            As[kq + 0][m] = v.x;
            As[kq + 1][m] = v.y;
            As[kq + 2][m] = v.z;
            As[kq + 3][m] = v.w;
        }
#pragma unroll
        for (int i = 0; i < 2; i++) {
            int t = tid + 256 * i;
            int k = t >> 5;
            int f = (t & 31) * 4;
            *(float4*)&Bs[k][f] = *(const float4*)(W + (size_t)(k0 + k) * FF + f);
        }
        __syncthreads();
#pragma unroll
        for (int kk = 0; kk < 16; kk++) {
            float4 a0 = *(const float4*)&As[kk][ty * 8];
            float4 a1 = *(const float4*)&As[kk][ty * 8 + 4];
            float4 b0 = *(const float4*)&Bs[kk][tx * 8];
            float4 b1 = *(const float4*)&Bs[kk][tx * 8 + 4];
            float ar[8] = {a0.x, a0.y, a0.z, a0.w, a1.x, a1.y, a1.z, a1.w};
            float br[8] = {b0.x, b0.y, b0.z, b0.w, b1.x, b1.y, b1.z, b1.w};
#pragma unroll
            for (int i = 0; i < 8; i++)
#pragma unroll
                for (int j = 0; j < 8; j++)
                    acc[i][j] += ar[i] * br[j];
        }
        __syncthreads();
    }

#pragma unroll
    for (int i = 0; i < 8; i++) {
        int n = m0 + ty * 8 + i;
        float* orow = out + (size_t)b * NN * FF + (size_t)n * FF;
#pragma unroll
        for (int j = 0; j < 8; j += 4) {
            int f = tx * 8 + j;
            float4 o;
            o.x = acc[i][j + 0];
            o.y = acc[i][j + 1];
            o.z = acc[i][j + 2];
            o.w = acc[i][j + 3];
            *(float4*)(orow + f) = o;
        }
    }
}

// ---------------------------------------------------------------------------
extern "C" void kernel_launch(void* const* d_in, const int* in_sizes, int n_in,
                              void* d_out, int out_size) {
    // Identify inputs by element count (robust to ordering).
    const float *X = nullptr, *A = nullptr, *W = nullptr;
    for (int i = 0; i < n_in; i++) {
        if (in_sizes[i] == BATCH * NN * FF)      X = (const float*)d_in[i];
        else if (in_sizes[i] == BATCH * NN * NN) A = (const float*)d_in[i];
        else if (in_sizes[i] == FF * FF)         W = (const float*)d_in[i];
    }
    float* out = (float*)d_out;

    // 1) degrees: one warp per row -> 16384 warps
    deg_kernel<<<(BATCH * NN * 32) / 256, 256>>>(A);
    // 2) scale X by d[m]
    scale_kernel<<<(BATCH * NN * FF / 4 + 255) / 256, 256>>>(X);
    // 3) Y = d[n]*(A @ Xs + Xs), per-batch GEMM, 128-row tiles
    bmm_kernel<<<dim3(NN / 128, BATCH), 256>>>(A);
    // 4) out = Y @ W
    wmul_kernel<<<dim3(NN / 128, BATCH), 256>>>(W, out);
}

// round 9
// speedup vs baseline: 1.6922x; 1.6922x over previous
#include <cuda_runtime.h>
#include <cuda_bf16.h>
#include <cstdint>

#define BATCH 16
#define NN 1024
#define FF 128

// ---------------- scratch (device globals: no allocs allowed) --------------
__device__ float g_dinv[BATCH * NN];              // 64 KB
__device__ float g_Zf[BATCH * NN * FF];           // 8 MB  Z = d_m*(X@W), fp32 [b][m][g]
__device__ __nv_bfloat16 g_Zh[BATCH * NN * FF];   // 4 MB  bf16 hi, [b][m][g]
__device__ __nv_bfloat16 g_Zl[BATCH * NN * FF];   // 4 MB  bf16 lo, [b][m][g]

// ---------------- helpers ---------------------------------------------------
__device__ __forceinline__ uint32_t smem_u32(const void* p) {
    uint32_t a;
    asm("{ .reg .u64 t; cvta.to.shared.u64 t, %1; cvt.u32.u64 %0, t; }"
        : "=r"(a) : "l"(p));
    return a;
}
__device__ __forceinline__ uint32_t pk(__nv_bfloat16 a, __nv_bfloat16 b) {
    return (uint32_t)__bfloat16_as_ushort(a) | ((uint32_t)__bfloat16_as_ushort(b) << 16);
}
__device__ __forceinline__ void ldsm4(uint32_t* r, uint32_t a) {
    asm volatile("ldmatrix.sync.aligned.m8n8.x4.shared.b16 {%0,%1,%2,%3}, [%4];"
                 : "=r"(r[0]), "=r"(r[1]), "=r"(r[2]), "=r"(r[3]) : "r"(a));
}
__device__ __forceinline__ void ldsm4t(uint32_t* r, uint32_t a) {
    asm volatile("ldmatrix.sync.aligned.m8n8.x4.trans.shared.b16 {%0,%1,%2,%3}, [%4];"
                 : "=r"(r[0]), "=r"(r[1]), "=r"(r[2]), "=r"(r[3]) : "r"(a));
}
__device__ __forceinline__ void mma16816(float* c, const uint32_t* a, const uint32_t* b) {
    asm volatile(
        "mma.sync.aligned.m16n8k16.row.col.f32.bf16.bf16.f32 "
        "{%0,%1,%2,%3}, {%4,%5,%6,%7}, {%8,%9}, {%0,%1,%2,%3};"
        : "+f"(c[0]), "+f"(c[1]), "+f"(c[2]), "+f"(c[3])
        : "r"(a[0]), "r"(a[1]), "r"(a[2]), "r"(a[3]), "r"(b[0]), "r"(b[1]));
}

// ---------------------------------------------------------------------------
// Kernel 1: row degree -> d_inv_sqrt. One warp per row of A.
// ---------------------------------------------------------------------------
__global__ void deg_kernel(const float* __restrict__ A) {
    int warp = (blockIdx.x * blockDim.x + threadIdx.x) >> 5;
    int lane = threadIdx.x & 31;
    if (warp >= BATCH * NN) return;
    const float4* row = (const float4*)(A + (size_t)warp * NN);
    float s = 0.f;
#pragma unroll
    for (int i = 0; i < 8; i++) {
        float4 v = row[lane + 32 * i];
        s += v.x + v.y + v.z + v.w;
    }
#pragma unroll
    for (int o = 16; o; o >>= 1) s += __shfl_xor_sync(0xffffffffu, s, o);
    if (lane == 0) g_dinv[warp] = rsqrtf(s + 1.0f);
}

// ---------------------------------------------------------------------------
// Kernel 2: Z = (d ⊙ X) @ W. Writes Zf fp32 and bf16 hi/lo, all [b][m][g].
// ---------------------------------------------------------------------------
__global__ void __launch_bounds__(256) z_kernel(const float* __restrict__ X,
                                                const float* __restrict__ W) {
    __shared__ float As[16][132];
    __shared__ float Bs[16][128];
    int b = blockIdx.y;
    int m0 = blockIdx.x * 128;
    const float* Xb = X + (size_t)b * NN * FF;
    int tid = threadIdx.x;
    int tx = tid & 15, ty = tid >> 4;

    float acc[8][8] = {};

    for (int k0 = 0; k0 < FF; k0 += 16) {
#pragma unroll
        for (int i = 0; i < 2; i++) {
            int t = tid + 256 * i;
            int m = t >> 2;
            int kq = (t & 3) * 4;
            float4 v = *(const float4*)(Xb + (size_t)(m0 + m) * FF + k0 + kq);
            As[kq + 0][m] = v.x; As[kq + 1][m] = v.y;
            As[kq + 2][m] = v.z; As[kq + 3][m] = v.w;
        }
#pragma unroll
        for (int i = 0; i < 2; i++) {
            int t = tid + 256 * i;
            int k = t >> 5;
            int f = (t & 31) * 4;
            *(float4*)&Bs[k][f] = *(const float4*)(W + (size_t)(k0 + k) * FF + f);
        }
        __syncthreads();
#pragma unroll
        for (int kk = 0; kk < 16; kk++) {
            float4 a0 = *(const float4*)&As[kk][ty * 8];
            float4 a1 = *(const float4*)&As[kk][ty * 8 + 4];
            float4 b0 = *(const float4*)&Bs[kk][tx * 8];
            float4 b1 = *(const float4*)&Bs[kk][tx * 8 + 4];
            float ar[8] = {a0.x, a0.y, a0.z, a0.w, a1.x, a1.y, a1.z, a1.w};
            float br[8] = {b0.x, b0.y, b0.z, b0.w, b1.x, b1.y, b1.z, b1.w};
#pragma unroll
            for (int i = 0; i < 8; i++)
#pragma unroll
                for (int j = 0; j < 8; j++)
                    acc[i][j] += ar[i] * br[j];
        }
        __syncthreads();
    }

#pragma unroll
    for (int i = 0; i < 8; i++) {
        int m = m0 + ty * 8 + i;
        float dm = g_dinv[b * NN + m];
        size_t rowoff = ((size_t)b * NN + m) * FF;
        float* zrow = g_Zf + rowoff;
#pragma unroll
        for (int j = 0; j < 8; j += 4) {
            int g = tx * 8 + j;
            float4 o;
            o.x = dm * acc[i][j + 0];
            o.y = dm * acc[i][j + 1];
            o.z = dm * acc[i][j + 2];
            o.w = dm * acc[i][j + 3];
            *(float4*)(zrow + g) = o;
            __nv_bfloat16 hx = __float2bfloat16(o.x), hy = __float2bfloat16(o.y);
            __nv_bfloat16 hz = __float2bfloat16(o.z), hw = __float2bfloat16(o.w);
            uint2 hv = { pk(hx, hy), pk(hz, hw) };
            *(uint2*)(g_Zh + rowoff + g) = hv;
            uint2 lv = { pk(__float2bfloat16(o.x - __bfloat162float(hx)),
                           __float2bfloat16(o.y - __bfloat162float(hy))),
                         pk(__float2bfloat16(o.z - __bfloat162float(hz)),
                           __float2bfloat16(o.w - __bfloat162float(hw))) };
            *(uint2*)(g_Zl + rowoff + g) = lv;
        }
    }
}

// ---------------------------------------------------------------------------
// Kernel 3: out[n,g] = d_n * ( sum_m A[n,m]*Z[m,g] + Z[n,g] ) via mma.sync bf16
// 3-pass hi/lo split (Ahi*Zhi + Ahi*Zlo + Alo*Zhi), fp32 accumulators.
// Block: 128(M) x 128(N). SYNCHRONOUS single-buffer mainloop, K chunk = 64.
// AST fixed 40 -> 72: a 64-bf16 (128B) A row needs stride >= 64 b16; 72 b16
// (144B) pads to a conflict-free ldsm pattern (144 mod 128 = 16).
// ---------------------------------------------------------------------------
#define AST 72              // A smem row stride (b16): 144B = 128B data + 16B pad
#define ZST 136             // Z smem row stride (b16): 272B = 256B data + 16B pad
#define AH_OFF 0
#define AL_OFF 18432        // 128*144
#define ZH_OFF 36864
#define ZL_OFF 54272        // +64*272
#define SMEM_TOTAL 71680    // +64*272

__global__ void __launch_bounds__(256) bmm_mma(const float* __restrict__ A,
                                               float* __restrict__ out) {
    extern __shared__ __align__(16) char smem[];
    uint32_t sb = smem_u32(smem);
    int tid = threadIdx.x, wid = tid >> 5, lane = tid & 31;
    int b = blockIdx.y, m0 = blockIdx.x * 128;
    int warp_m = wid >> 1, warp_n = wid & 1;   // 4 x 2 warps, warp tile 32x64

    const float* Ab = A + (size_t)b * NN * NN + (size_t)m0 * NN;
    const __nv_bfloat16* Zh = g_Zh + (size_t)b * NN * FF;
    const __nv_bfloat16* Zl = g_Zl + (size_t)b * NN * FF;

    // ldmatrix lane offsets (bytes)
    int a_row = (lane & 7) + ((lane >> 3) & 1) * 8;   // m within 16x16 tile
    int a_colb = (lane >> 4) * 16;                    // k byte offset (0 | 16)
    uint32_t a_loff = (uint32_t)((warp_m * 32 + a_row) * (AST * 2) + a_colb);
    int b_rowk = (lane & 7) + ((lane >> 3) & 1) * 8;  // k within 16x16 tile
    int b_noff = (lane >> 4) * 8;                     // n offset (0 | 8)
    uint32_t b_loff = (uint32_t)(b_rowk * (ZST * 2) + (warp_n * 64 + b_noff) * 2);

    float acc[2][8][4];
#pragma unroll
    for (int f = 0; f < 2; f++)
#pragma unroll
        for (int j = 0; j < 8; j++)
#pragma unroll
            for (int c = 0; c < 4; c++) acc[f][j][c] = 0.f;

    for (int it = 0; it < 16; ++it) {
        int k0 = it * 64;
        __syncthreads();   // protect previous iteration's reads

        // ---- stage A chunk: 128 rows x 64 fp32 -> bf16 hi/lo ----
#pragma unroll
        for (int q = 0; q < 8; q++) {
            int t = tid + 256 * q;           // 0..2047
            int r = t >> 4;                  // 0..127
            int c4 = (t & 15) * 4;           // 0..60
            float4 v = *(const float4*)(Ab + (size_t)r * NN + k0 + c4);
            __nv_bfloat16 hx = __float2bfloat16(v.x), hy = __float2bfloat16(v.y);
            __nv_bfloat16 hz = __float2bfloat16(v.z), hw = __float2bfloat16(v.w);
            uint2 hv = { pk(hx, hy), pk(hz, hw) };
            uint2 lv = { pk(__float2bfloat16(v.x - __bfloat162float(hx)),
                           __float2bfloat16(v.y - __bfloat162float(hy))),
                         pk(__float2bfloat16(v.z - __bfloat162float(hz)),
                           __float2bfloat16(v.w - __bfloat162float(hw))) };
            uint32_t off = (uint32_t)(r * (AST * 2) + c4 * 2);
            *(uint2*)(smem + AH_OFF + off) = hv;
            *(uint2*)(smem + AL_OFF + off) = lv;
        }
        // ---- stage Z chunk: 64 k-rows x 128 g (hi & lo, already bf16) ----
#pragma unroll
        for (int q = 0; q < 4; q++) {
            int t = tid + 256 * q;           // 0..1023
            int row = t >> 4;                // 0..63
            int g16 = (t & 15) * 16;         // byte offset 0..240
            uint32_t off = (uint32_t)(row * (ZST * 2) + g16);
            *(uint4*)(smem + ZH_OFF + off) =
                *(const uint4*)((const char*)(Zh + (size_t)(k0 + row) * FF) + g16);
            *(uint4*)(smem + ZL_OFF + off) =
                *(const uint4*)((const char*)(Zl + (size_t)(k0 + row) * FF) + g16);
        }
        __syncthreads();

        // ---- compute: 4 k16 steps x (2 m-halves x 8 n8 x 3 passes) ----
#pragma unroll
        for (int ks = 0; ks < 4; ks++) {
            uint32_t ahi[2][4], alo[2][4], zh[4][4], zl[4][4];
#pragma unroll
            for (int f = 0; f < 2; f++) {
                uint32_t ao = sb + a_loff + (uint32_t)(f * 16 * AST * 2 + ks * 32);
                ldsm4(ahi[f], ao + AH_OFF);
                ldsm4(alo[f], ao + AL_OFF);
            }
#pragma unroll
            for (int jj = 0; jj < 4; jj++) {
                uint32_t bo = sb + b_loff + (uint32_t)(ks * 16 * ZST * 2 + jj * 32);
                ldsm4t(zh[jj], bo + ZH_OFF);
                ldsm4t(zl[jj], bo + ZL_OFF);
            }
#pragma unroll
            for (int f = 0; f < 2; f++)
#pragma unroll
                for (int j = 0; j < 8; j++) {
                    mma16816(acc[f][j], ahi[f], &zh[j >> 1][(j & 1) * 2]);
                    mma16816(acc[f][j], ahi[f], &zl[j >> 1][(j & 1) * 2]);
                    mma16816(acc[f][j], alo[f], &zh[j >> 1][(j & 1) * 2]);
                }
        }
    }

    // ---- epilogue: acc + Z identity, scale by d_n ----
    int grp = lane >> 2, qid = lane & 3;
#pragma unroll
    for (int f = 0; f < 2; f++) {
        int r0 = m0 + warp_m * 32 + f * 16 + grp;
        int r1 = r0 + 8;
        float d0 = g_dinv[b * NN + r0];
        float d1 = g_dinv[b * NN + r1];
        const float* z0 = g_Zf + ((size_t)b * NN + r0) * FF;
        const float* z1 = g_Zf + ((size_t)b * NN + r1) * FF;
        float* o0 = out + ((size_t)b * NN + r0) * FF;
        float* o1 = out + ((size_t)b * NN + r1) * FF;
#pragma unroll
        for (int j = 0; j < 8; j++) {
            int g = warp_n * 64 + j * 8 + qid * 2;
            float2 za = *(const float2*)(z0 + g);
            float2 zb = *(const float2*)(z1 + g);
            float2 oa, ob;
            oa.x = d0 * (acc[f][j][0] + za.x);
            oa.y = d0 * (acc[f][j][1] + za.y);
            ob.x = d1 * (acc[f][j][2] + zb.x);
            ob.y = d1 * (acc[f][j][3] + zb.y);
            *(float2*)(o0 + g) = oa;
            *(float2*)(o1 + g) = ob;
        }
    }
}

// ---------------------------------------------------------------------------
extern "C" void kernel_launch(void* const* d_in, const int* in_sizes, int n_in,
                              void* d_out, int out_size) {
    const float *X = nullptr, *A = nullptr, *W = nullptr;
    for (int i = 0; i < n_in; i++) {
        if (in_sizes[i] == BATCH * NN * FF)      X = (const float*)d_in[i];
        else if (in_sizes[i] == BATCH * NN * NN) A = (const float*)d_in[i];
        else if (in_sizes[i] == FF * FF)         W = (const float*)d_in[i];
    }
    float* out = (float*)d_out;

    cudaFuncSetAttribute(bmm_mma, cudaFuncAttributeMaxDynamicSharedMemorySize,
                         SMEM_TOTAL);

    deg_kernel<<<(BATCH * NN * 32) / 256, 256>>>(A);
    z_kernel<<<dim3(NN / 128, BATCH), 256>>>(X, W);
    bmm_mma<<<dim3(NN / 128, BATCH), 256, SMEM_TOTAL>>>(A, out);
}

// round 11
// speedup vs baseline: 1.9030x; 1.1245x over previous
#include <cuda_runtime.h>
#include <cuda_bf16.h>
#include <cstdint>

#define BATCH 16
#define NN 1024
#define FF 128

// ---------------- scratch (device globals: no allocs allowed) --------------
__device__ float g_dinv[BATCH * NN];              // 64 KB
__device__ float g_Zf[BATCH * NN * FF];           // 8 MB  Z = d_m*(X@W), fp32 [b][m][g]
__device__ __nv_bfloat16 g_Zh[BATCH * NN * FF];   // 4 MB  bf16 hi, [b][m][g]
__device__ __nv_bfloat16 g_Zl[BATCH * NN * FF];   // 4 MB  bf16 lo, [b][m][g]

// ---------------- helpers ---------------------------------------------------
__device__ __forceinline__ uint32_t smem_u32(const void* p) {
    uint32_t a;
    asm("{ .reg .u64 t; cvta.to.shared.u64 t, %1; cvt.u32.u64 %0, t; }"
        : "=r"(a) : "l"(p));
    return a;
}
__device__ __forceinline__ uint32_t pk(__nv_bfloat16 a, __nv_bfloat16 b) {
    return (uint32_t)__bfloat16_as_ushort(a) | ((uint32_t)__bfloat16_as_ushort(b) << 16);
}
__device__ __forceinline__ void ldsm4(uint32_t* r, uint32_t a) {
    asm volatile("ldmatrix.sync.aligned.m8n8.x4.shared.b16 {%0,%1,%2,%3}, [%4];"
                 : "=r"(r[0]), "=r"(r[1]), "=r"(r[2]), "=r"(r[3]) : "r"(a));
}
__device__ __forceinline__ void ldsm4t(uint32_t* r, uint32_t a) {
    asm volatile("ldmatrix.sync.aligned.m8n8.x4.trans.shared.b16 {%0,%1,%2,%3}, [%4];"
                 : "=r"(r[0]), "=r"(r[1]), "=r"(r[2]), "=r"(r[3]) : "r"(a));
}
__device__ __forceinline__ void mma16816(float* c, const uint32_t* a, const uint32_t* b) {
    asm volatile(
        "mma.sync.aligned.m16n8k16.row.col.f32.bf16.bf16.f32 "
        "{%0,%1,%2,%3}, {%4,%5,%6,%7}, {%8,%9}, {%0,%1,%2,%3};"
        : "+f"(c[0]), "+f"(c[1]), "+f"(c[2]), "+f"(c[3])
        : "r"(a[0]), "r"(a[1]), "r"(a[2]), "r"(a[3]), "r"(b[0]), "r"(b[1]));
}
#define CPA16(dst, src) \
    asm volatile("cp.async.cg.shared.global [%0], [%1], 16;" :: "r"(dst), "l"(src))
#define CPA_COMMIT() asm volatile("cp.async.commit_group;" ::: "memory")
#define CPA_WAIT0()  asm volatile("cp.async.wait_group 0;" ::: "memory")

// ---------------------------------------------------------------------------
// Kernel 1: row degree -> d_inv_sqrt. One warp per row of A.
// ---------------------------------------------------------------------------
__global__ void deg_kernel(const float* __restrict__ A) {
    int warp = (blockIdx.x * blockDim.x + threadIdx.x) >> 5;
    int lane = threadIdx.x & 31;
    if (warp >= BATCH * NN) return;
    const float4* row = (const float4*)(A + (size_t)warp * NN);
    float s = 0.f;
#pragma unroll
    for (int i = 0; i < 8; i++) {
        float4 v = row[lane + 32 * i];
        s += v.x + v.y + v.z + v.w;
    }
#pragma unroll
    for (int o = 16; o; o >>= 1) s += __shfl_xor_sync(0xffffffffu, s, o);
    if (lane == 0) g_dinv[warp] = rsqrtf(s + 1.0f);
}

// ---------------------------------------------------------------------------
// Kernel 2: Z = (d ⊙ X) @ W. Writes Zf fp32 and bf16 hi/lo, all [b][m][g].
// ---------------------------------------------------------------------------
__global__ void __launch_bounds__(256) z_kernel(const float* __restrict__ X,
                                                const float* __restrict__ W) {
    __shared__ float As[16][132];
    __shared__ float Bs[16][128];
    int b = blockIdx.y;
    int m0 = blockIdx.x * 128;
    const float* Xb = X + (size_t)b * NN * FF;
    int tid = threadIdx.x;
    int tx = tid & 15, ty = tid >> 4;

    float acc[8][8] = {};

    for (int k0 = 0; k0 < FF; k0 += 16) {
#pragma unroll
        for (int i = 0; i < 2; i++) {
            int t = tid + 256 * i;
            int m = t >> 2;
            int kq = (t & 3) * 4;
            float4 v = *(const float4*)(Xb + (size_t)(m0 + m) * FF + k0 + kq);
            As[kq + 0][m] = v.x; As[kq + 1][m] = v.y;
            As[kq + 2][m] = v.z; As[kq + 3][m] = v.w;
        }
#pragma unroll
        for (int i = 0; i < 2; i++) {
            int t = tid + 256 * i;
            int k = t >> 5;
            int f = (t & 31) * 4;
            *(float4*)&Bs[k][f] = *(const float4*)(W + (size_t)(k0 + k) * FF + f);
        }
        __syncthreads();
#pragma unroll
        for (int kk = 0; kk < 16; kk++) {
            float4 a0 = *(const float4*)&As[kk][ty * 8];
            float4 a1 = *(const float4*)&As[kk][ty * 8 + 4];
            float4 b0 = *(const float4*)&Bs[kk][tx * 8];
            float4 b1 = *(const float4*)&Bs[kk][tx * 8 + 4];
            float ar[8] = {a0.x, a0.y, a0.z, a0.w, a1.x, a1.y, a1.z, a1.w};
            float br[8] = {b0.x, b0.y, b0.z, b0.w, b1.x, b1.y, b1.z, b1.w};
#pragma unroll
            for (int i = 0; i < 8; i++)
#pragma unroll
                for (int j = 0; j < 8; j++)
                    acc[i][j] += ar[i] * br[j];
        }
        __syncthreads();
    }

#pragma unroll
    for (int i = 0; i < 8; i++) {
        int m = m0 + ty * 8 + i;
        float dm = g_dinv[b * NN + m];
        size_t rowoff = ((size_t)b * NN + m) * FF;
        float* zrow = g_Zf + rowoff;
#pragma unroll
        for (int j = 0; j < 8; j += 4) {
            int g = tx * 8 + j;
            float4 o;
            o.x = dm * acc[i][j + 0];
            o.y = dm * acc[i][j + 1];
            o.z = dm * acc[i][j + 2];
            o.w = dm * acc[i][j + 3];
            *(float4*)(zrow + g) = o;
            __nv_bfloat16 hx = __float2bfloat16(o.x), hy = __float2bfloat16(o.y);
            __nv_bfloat16 hz = __float2bfloat16(o.z), hw = __float2bfloat16(o.w);
            uint2 hv = { pk(hx, hy), pk(hz, hw) };
            *(uint2*)(g_Zh + rowoff + g) = hv;
            uint2 lv = { pk(__float2bfloat16(o.x - __bfloat162float(hx)),
                           __float2bfloat16(o.y - __bfloat162float(hy))),
                         pk(__float2bfloat16(o.z - __bfloat162float(hz)),
                           __float2bfloat16(o.w - __bfloat162float(hw))) };
            *(uint2*)(g_Zl + rowoff + g) = lv;
        }
    }
}

// ---------------------------------------------------------------------------
// Kernel 3: out[n,g] = d_n * ( sum_m A[n,m]*Z[m,g] + Z[n,g] ) via mma.sync bf16
// 3-pass hi/lo split (Ahi*Zhi + Ahi*Zlo + Alo*Zhi), fp32 accumulators.
// Block: 128(M) x 128(N), K chunk = 64, DOUBLE-BUFFERED:
//   per iter: LDG A(next)->regs; cp.async Z(next)->other buf; compute(cur);
//             convert+STS A(next); wait; sync.
// Layout identical to the R9-green kernel (AST=72, ZST=136).
// ---------------------------------------------------------------------------
#define AST 72              // A smem row stride (b16): 144B = 128B data + 16B pad
#define ZST 136             // Z smem row stride (b16): 272B = 256B data + 16B pad
#define AH_OFF 0
#define AL_OFF 18432        // 128*144
#define ZH_OFF 36864
#define ZL_OFF 54272        // +64*272
#define BUF_B  71680        // +64*272
#define SMEM_TOTAL (2 * BUF_B)   // 143360

__global__ void __launch_bounds__(256) bmm_mma(const float* __restrict__ A,
                                               float* __restrict__ out) {
    extern __shared__ __align__(16) char smem[];
    uint32_t sb = smem_u32(smem);
    int tid = threadIdx.x, wid = tid >> 5, lane = tid & 31;
    int b = blockIdx.y, m0 = blockIdx.x * 128;
    int warp_m = wid >> 1, warp_n = wid & 1;   // 4 x 2 warps, warp tile 32x64

    const float* Ab = A + (size_t)b * NN * NN + (size_t)m0 * NN;
    const __nv_bfloat16* Zh = g_Zh + (size_t)b * NN * FF;
    const __nv_bfloat16* Zl = g_Zl + (size_t)b * NN * FF;

    // ldmatrix lane offsets (bytes)
    int a_row = (lane & 7) + ((lane >> 3) & 1) * 8;   // m within 16x16 tile
    int a_colb = (lane >> 4) * 16;                    // k byte offset (0 | 16)
    uint32_t a_loff = (uint32_t)((warp_m * 32 + a_row) * (AST * 2) + a_colb);
    int b_rowk = (lane & 7) + ((lane >> 3) & 1) * 8;  // k within 16x16 tile
    int b_noff = (lane >> 4) * 8;                     // n offset (0 | 8)
    uint32_t b_loff = (uint32_t)(b_rowk * (ZST * 2) + (warp_n * 64 + b_noff) * 2);

    float acc[2][8][4];
#pragma unroll
    for (int f = 0; f < 2; f++)
#pragma unroll
        for (int j = 0; j < 8; j++)
#pragma unroll
            for (int c = 0; c < 4; c++) acc[f][j][c] = 0.f;

    // ---- prologue: fill buffer 0 with chunk 0 ----
    {
        float4 areg[8];
#pragma unroll
        for (int q = 0; q < 8; q++) {
            int t = tid + 256 * q;
            int r = t >> 4, c4 = (t & 15) * 4;
            areg[q] = *(const float4*)(Ab + (size_t)r * NN + c4);
        }
#pragma unroll
        for (int q = 0; q < 4; q++) {
            int t = tid + 256 * q;
            int row = t >> 4, g16 = (t & 15) * 16;
            uint32_t off = (uint32_t)(row * (ZST * 2) + g16);
            CPA16(sb + ZH_OFF + off, (const char*)(Zh + (size_t)row * FF) + g16);
            CPA16(sb + ZL_OFF + off, (const char*)(Zl + (size_t)row * FF) + g16);
        }
        CPA_COMMIT();
#pragma unroll
        for (int q = 0; q < 8; q++) {
            int t = tid + 256 * q;
            int r = t >> 4, c4 = (t & 15) * 4;
            float4 v = areg[q];
            __nv_bfloat16 hx = __float2bfloat16(v.x), hy = __float2bfloat16(v.y);
            __nv_bfloat16 hz = __float2bfloat16(v.z), hw = __float2bfloat16(v.w);
            uint2 hv = { pk(hx, hy), pk(hz, hw) };
            uint2 lv = { pk(__float2bfloat16(v.x - __bfloat162float(hx)),
                           __float2bfloat16(v.y - __bfloat162float(hy))),
                         pk(__float2bfloat16(v.z - __bfloat162float(hz)),
                           __float2bfloat16(v.w - __bfloat162float(hw))) };
            uint32_t off = (uint32_t)(r * (AST * 2) + c4 * 2);
            *(uint2*)(smem + AH_OFF + off) = hv;
            *(uint2*)(smem + AL_OFF + off) = lv;
        }
        CPA_WAIT0();
        __syncthreads();
    }

    for (int it = 0; it < 16; ++it) {
        uint32_t cb = sb + (uint32_t)((it & 1) * BUF_B);      // compute buffer
        char* np = smem + ((it + 1) & 1) * BUF_B;             // next (staging) buffer
        uint32_t nb = sb + (uint32_t)(((it + 1) & 1) * BUF_B);
        int k0n = (it + 1) * 64;
        bool has_next = (it + 1 < 16);

        // ---- (1) next A chunk -> registers ----
        float4 areg[8];
        if (has_next) {
#pragma unroll
            for (int q = 0; q < 8; q++) {
                int t = tid + 256 * q;
                int r = t >> 4, c4 = (t & 15) * 4;
                areg[q] = *(const float4*)(Ab + (size_t)r * NN + k0n + c4);
            }
            // ---- (2) next Z chunk via cp.async ----
#pragma unroll
            for (int q = 0; q < 4; q++) {
                int t = tid + 256 * q;
                int row = t >> 4, g16 = (t & 15) * 16;
                uint32_t off = (uint32_t)(row * (ZST * 2) + g16);
                CPA16(nb + ZH_OFF + off,
                      (const char*)(Zh + (size_t)(k0n + row) * FF) + g16);
                CPA16(nb + ZL_OFF + off,
                      (const char*)(Zl + (size_t)(k0n + row) * FF) + g16);
            }
            CPA_COMMIT();
        }

        // ---- (3) compute current chunk: 4 k16 steps ----
#pragma unroll
        for (int ks = 0; ks < 4; ks++) {
            uint32_t ahi[2][4], alo[2][4], zh[4][4], zl[4][4];
#pragma unroll
            for (int f = 0; f < 2; f++) {
                uint32_t ao = cb + a_loff + (uint32_t)(f * 16 * AST * 2 + ks * 32);
                ldsm4(ahi[f], ao + AH_OFF);
                ldsm4(alo[f], ao + AL_OFF);
            }
#pragma unroll
            for (int jj = 0; jj < 4; jj++) {
                uint32_t bo = cb + b_loff + (uint32_t)(ks * 16 * ZST * 2 + jj * 32);
                ldsm4t(zh[jj], bo + ZH_OFF);
                ldsm4t(zl[jj], bo + ZL_OFF);
            }
#pragma unroll
            for (int f = 0; f < 2; f++)
#pragma unroll
                for (int j = 0; j < 8; j++) {
                    mma16816(acc[f][j], ahi[f], &zh[j >> 1][(j & 1) * 2]);
                    mma16816(acc[f][j], ahi[f], &zl[j >> 1][(j & 1) * 2]);
                    mma16816(acc[f][j], alo[f], &zh[j >> 1][(j & 1) * 2]);
                }
        }

        // ---- (4) convert + STS next A chunk; (5) drain cp.async; sync ----
        if (has_next) {
#pragma unroll
            for (int q = 0; q < 8; q++) {
                int t = tid + 256 * q;
                int r = t >> 4, c4 = (t & 15) * 4;
                float4 v = areg[q];
                __nv_bfloat16 hx = __float2bfloat16(v.x), hy = __float2bfloat16(v.y);
                __nv_bfloat16 hz = __float2bfloat16(v.z), hw = __float2bfloat16(v.w);
                uint2 hv = { pk(hx, hy), pk(hz, hw) };
                uint2 lv = { pk(__float2bfloat16(v.x - __bfloat162float(hx)),
                               __float2bfloat16(v.y - __bfloat162float(hy))),
                             pk(__float2bfloat16(v.z - __bfloat162float(hz)),
                               __float2bfloat16(v.w - __bfloat162float(hw))) };
                uint32_t off = (uint32_t)(r * (AST * 2) + c4 * 2);
                *(uint2*)(np + AH_OFF + off) = hv;
                *(uint2*)(np + AL_OFF + off) = lv;
            }
            CPA_WAIT0();
            __syncthreads();
        }
    }

    // ---- epilogue: acc + Z identity, scale by d_n ----
    int grp = lane >> 2, qid = lane & 3;
#pragma unroll
    for (int f = 0; f < 2; f++) {
        int r0 = m0 + warp_m * 32 + f * 16 + grp;
        int r1 = r0 + 8;
        float d0 = g_dinv[b * NN + r0];
        float d1 = g_dinv[b * NN + r1];
        const float* z0 = g_Zf + ((size_t)b * NN + r0) * FF;
        const float* z1 = g_Zf + ((size_t)b * NN + r1) * FF;
        float* o0 = out + ((size_t)b * NN + r0) * FF;
        float* o1 = out + ((size_t)b * NN + r1) * FF;
#pragma unroll
        for (int j = 0; j < 8; j++) {
            int g = warp_n * 64 + j * 8 + qid * 2;
            float2 za = *(const float2*)(z0 + g);
            float2 zb = *(const float2*)(z1 + g);
            float2 oa, ob;
            oa.x = d0 * (acc[f][j][0] + za.x);
            oa.y = d0 * (acc[f][j][1] + za.y);
            ob.x = d1 * (acc[f][j][2] + zb.x);
            ob.y = d1 * (acc[f][j][3] + zb.y);
            *(float2*)(o0 + g) = oa;
            *(float2*)(o1 + g) = ob;
        }
    }
}

// ---------------------------------------------------------------------------
extern "C" void kernel_launch(void* const* d_in, const int* in_sizes, int n_in,
                              void* d_out, int out_size) {
    const float *X = nullptr, *A = nullptr, *W = nullptr;
    for (int i = 0; i < n_in; i++) {
        if (in_sizes[i] == BATCH * NN * FF)      X = (const float*)d_in[i];
        else if (in_sizes[i] == BATCH * NN * NN) A = (const float*)d_in[i];
        else if (in_sizes[i] == FF * FF)         W = (const float*)d_in[i];
    }
    float* out = (float*)d_out;

    cudaFuncSetAttribute(bmm_mma, cudaFuncAttributeMaxDynamicSharedMemorySize,
                         SMEM_TOTAL);

    deg_kernel<<<(BATCH * NN * 32) / 256, 256>>>(A);
    z_kernel<<<dim3(NN / 128, BATCH), 256>>>(X, W);
    bmm_mma<<<dim3(NN / 128, BATCH), 256, SMEM_TOTAL>>>(A, out);
}

// round 13
// speedup vs baseline: 2.0394x; 1.0717x over previous
#include <cuda_runtime.h>
#include <cuda_bf16.h>
#include <cstdint>

#define BATCH 16
#define NN 1024
#define FF 128

// ---------------- scratch (device globals: no allocs allowed) --------------
__device__ float g_dinv[BATCH * NN];              // 64 KB
__device__ float g_Zf[BATCH * NN * FF];           // 8 MB  Z = d_m*(X@W), fp32 [b][m][g]
__device__ __nv_bfloat16 g_Zh[BATCH * NN * FF];   // 4 MB  bf16 hi, [b][m][g]
__device__ __nv_bfloat16 g_Zl[BATCH * NN * FF];   // 4 MB  bf16 lo, [b][m][g]

// ---------------- helpers ---------------------------------------------------
__device__ __forceinline__ uint32_t smem_u32(const void* p) {
    uint32_t a;
    asm("{ .reg .u64 t; cvta.to.shared.u64 t, %1; cvt.u32.u64 %0, t; }"
        : "=r"(a) : "l"(p));
    return a;
}
__device__ __forceinline__ uint32_t pk(__nv_bfloat16 a, __nv_bfloat16 b) {
    return (uint32_t)__bfloat16_as_ushort(a) | ((uint32_t)__bfloat16_as_ushort(b) << 16);
}
__device__ __forceinline__ void ldsm4(uint32_t* r, uint32_t a) {
    asm volatile("ldmatrix.sync.aligned.m8n8.x4.shared.b16 {%0,%1,%2,%3}, [%4];"
                 : "=r"(r[0]), "=r"(r[1]), "=r"(r[2]), "=r"(r[3]) : "r"(a));
}
__device__ __forceinline__ void ldsm4t(uint32_t* r, uint32_t a) {
    asm volatile("ldmatrix.sync.aligned.m8n8.x4.trans.shared.b16 {%0,%1,%2,%3}, [%4];"
                 : "=r"(r[0]), "=r"(r[1]), "=r"(r[2]), "=r"(r[3]) : "r"(a));
}
__device__ __forceinline__ void mma16816(float* c, const uint32_t* a, const uint32_t* b) {
    asm volatile(
        "mma.sync.aligned.m16n8k16.row.col.f32.bf16.bf16.f32 "
        "{%0,%1,%2,%3}, {%4,%5,%6,%7}, {%8,%9}, {%0,%1,%2,%3};"
        : "+f"(c[0]), "+f"(c[1]), "+f"(c[2]), "+f"(c[3])
        : "r"(a[0]), "r"(a[1]), "r"(a[2]), "r"(a[3]), "r"(b[0]), "r"(b[1]));
}
#define CPA16(dst, src) \
    asm volatile("cp.async.cg.shared.global [%0], [%1], 16;" :: "r"(dst), "l"(src))
#define CPA_COMMIT() asm volatile("cp.async.commit_group;" ::: "memory")
#define CPA_WAIT0()  asm volatile("cp.async.wait_group 0;" ::: "memory")

// ---------------------------------------------------------------------------
// Kernel 1: row degree -> d_inv_sqrt. One warp per row of A.
// ---------------------------------------------------------------------------
__global__ void deg_kernel(const float* __restrict__ A) {
    int warp = (blockIdx.x * blockDim.x + threadIdx.x) >> 5;
    int lane = threadIdx.x & 31;
    if (warp >= BATCH * NN) return;
    const float4* row = (const float4*)(A + (size_t)warp * NN);
    float s = 0.f;
#pragma unroll
    for (int i = 0; i < 8; i++) {
        float4 v = row[lane + 32 * i];
        s += v.x + v.y + v.z + v.w;
    }
#pragma unroll
    for (int o = 16; o; o >>= 1) s += __shfl_xor_sync(0xffffffffu, s, o);
    if (lane == 0) g_dinv[warp] = rsqrtf(s + 1.0f);
}

// ---------------------------------------------------------------------------
// Kernel 2: Z = (d ⊙ X) @ W. Writes Zf fp32 and bf16 hi/lo, all [b][m][g].
// ---------------------------------------------------------------------------
__global__ void __launch_bounds__(256) z_kernel(const float* __restrict__ X,
                                                const float* __restrict__ W) {
    __shared__ float As[16][132];
    __shared__ float Bs[16][128];
    int b = blockIdx.y;
    int m0 = blockIdx.x * 128;
    const float* Xb = X + (size_t)b * NN * FF;
    int tid = threadIdx.x;
    int tx = tid & 15, ty = tid >> 4;

    float acc[8][8] = {};

    for (int k0 = 0; k0 < FF; k0 += 16) {
#pragma unroll
        for (int i = 0; i < 2; i++) {
            int t = tid + 256 * i;
            int m = t >> 2;
            int kq = (t & 3) * 4;
            float4 v = *(const float4*)(Xb + (size_t)(m0 + m) * FF + k0 + kq);
            As[kq + 0][m] = v.x; As[kq + 1][m] = v.y;
            As[kq + 2][m] = v.z; As[kq + 3][m] = v.w;
        }
#pragma unroll
        for (int i = 0; i < 2; i++) {
            int t = tid + 256 * i;
            int k = t >> 5;
            int f = (t & 31) * 4;
            *(float4*)&Bs[k][f] = *(const float4*)(W + (size_t)(k0 + k) * FF + f);
        }
        __syncthreads();
#pragma unroll
        for (int kk = 0; kk < 16; kk++) {
            float4 a0 = *(const float4*)&As[kk][ty * 8];
            float4 a1 = *(const float4*)&As[kk][ty * 8 + 4];
            float4 b0 = *(const float4*)&Bs[kk][tx * 8];
            float4 b1 = *(const float4*)&Bs[kk][tx * 8 + 4];
            float ar[8] = {a0.x, a0.y, a0.z, a0.w, a1.x, a1.y, a1.z, a1.w};
            float br[8] = {b0.x, b0.y, b0.z, b0.w, b1.x, b1.y, b1.z, b1.w};
#pragma unroll
            for (int i = 0; i < 8; i++)
#pragma unroll
                for (int j = 0; j < 8; j++)
                    acc[i][j] += ar[i] * br[j];
        }
        __syncthreads();
    }

#pragma unroll
    for (int i = 0; i < 8; i++) {
        int m = m0 + ty * 8 + i;
        float dm = g_dinv[b * NN + m];
        size_t rowoff = ((size_t)b * NN + m) * FF;
        float* zrow = g_Zf + rowoff;
#pragma unroll
        for (int j = 0; j < 8; j += 4) {
            int g = tx * 8 + j;
            float4 o;
            o.x = dm * acc[i][j + 0];
            o.y = dm * acc[i][j + 1];
            o.z = dm * acc[i][j + 2];
            o.w = dm * acc[i][j + 3];
            *(float4*)(zrow + g) = o;
            __nv_bfloat16 hx = __float2bfloat16(o.x), hy = __float2bfloat16(o.y);
            __nv_bfloat16 hz = __float2bfloat16(o.z), hw = __float2bfloat16(o.w);
            uint2 hv = { pk(hx, hy), pk(hz, hw) };
            *(uint2*)(g_Zh + rowoff + g) = hv;
            uint2 lv = { pk(__float2bfloat16(o.x - __bfloat162float(hx)),
                           __float2bfloat16(o.y - __bfloat162float(hy))),
                         pk(__float2bfloat16(o.z - __bfloat162float(hz)),
                           __float2bfloat16(o.w - __bfloat162float(hw))) };
            *(uint2*)(g_Zl + rowoff + g) = lv;
        }
    }
}

// ---------------------------------------------------------------------------
// Kernel 3: out[n,g] = d_n * ( sum_m A[n,m]*Z[m,g] + Z[n,g] ) via mma.sync bf16
// 3-pass hi/lo split, fp32 accumulators. Block tile 128x128, K chunk 64,
// double-buffered. NOW 512 threads / 16 warps (4x4), warp tile 32x32 for
// latency hiding (4 warps/SMSP instead of 2).
// ---------------------------------------------------------------------------
#define AST 72              // A smem row stride (b16): 144B = 128B data + 16B pad
#define ZST 136             // Z smem row stride (b16): 272B = 256B data + 16B pad
#define AH_OFF 0
#define AL_OFF 18432        // 128*144
#define ZH_OFF 36864
#define ZL_OFF 54272        // +64*272
#define BUF_B  71680        // +64*272
#define SMEM_TOTAL (2 * BUF_B)   // 143360

__global__ void __launch_bounds__(512) bmm_mma(const float* __restrict__ A,
                                               float* __restrict__ out) {
    extern __shared__ __align__(16) char smem[];
    uint32_t sb = smem_u32(smem);
    int tid = threadIdx.x, wid = tid >> 5, lane = tid & 31;
    int b = blockIdx.y, m0 = blockIdx.x * 128;
    int warp_m = wid >> 2, warp_n = wid & 3;   // 4 x 4 warps, warp tile 32x32

    const float* Ab = A + (size_t)b * NN * NN + (size_t)m0 * NN;
    const __nv_bfloat16* Zh = g_Zh + (size_t)b * NN * FF;
    const __nv_bfloat16* Zl = g_Zl + (size_t)b * NN * FF;

    // ldmatrix lane offsets (bytes)
    int a_row = (lane & 7) + ((lane >> 3) & 1) * 8;   // m within 16x16 tile
    int a_colb = (lane >> 4) * 16;                    // k byte offset (0 | 16)
    uint32_t a_loff = (uint32_t)((warp_m * 32 + a_row) * (AST * 2) + a_colb);
    int b_rowk = (lane & 7) + ((lane >> 3) & 1) * 8;  // k within 16x16 tile
    int b_noff = (lane >> 4) * 8;                     // n offset (0 | 8)
    uint32_t b_loff = (uint32_t)(b_rowk * (ZST * 2) + (warp_n * 32 + b_noff) * 2);

    float acc[2][4][4];
#pragma unroll
    for (int f = 0; f < 2; f++)
#pragma unroll
        for (int j = 0; j < 4; j++)
#pragma unroll
            for (int c = 0; c < 4; c++) acc[f][j][c] = 0.f;

    // ---- prologue: fill buffer 0 with chunk 0 ----
    {
        float4 areg[4];
#pragma unroll
        for (int q = 0; q < 4; q++) {
            int t = tid + 512 * q;           // 0..2047
            int r = t >> 4, c4 = (t & 15) * 4;
            areg[q] = *(const float4*)(Ab + (size_t)r * NN + c4);
        }
#pragma unroll
        for (int q = 0; q < 2; q++) {
            int t = tid + 512 * q;           // 0..1023
            int row = t >> 4, g16 = (t & 15) * 16;
            uint32_t off = (uint32_t)(row * (ZST * 2) + g16);
            CPA16(sb + ZH_OFF + off, (const char*)(Zh + (size_t)row * FF) + g16);
            CPA16(sb + ZL_OFF + off, (const char*)(Zl + (size_t)row * FF) + g16);
        }
        CPA_COMMIT();
#pragma unroll
        for (int q = 0; q < 4; q++) {
            int t = tid + 512 * q;
            int r = t >> 4, c4 = (t & 15) * 4;
            float4 v = areg[q];
            __nv_bfloat16 hx = __float2bfloat16(v.x), hy = __float2bfloat16(v.y);
            __nv_bfloat16 hz = __float2bfloat16(v.z), hw = __float2bfloat16(v.w);
            uint2 hv = { pk(hx, hy), pk(hz, hw) };
            uint2 lv = { pk(__float2bfloat16(v.x - __bfloat162float(hx)),
                           __float2bfloat16(v.y - __bfloat162float(hy))),
                         pk(__float2bfloat16(v.z - __bfloat162float(hz)),
                           __float2bfloat16(v.w - __bfloat162float(hw))) };
            uint32_t off = (uint32_t)(r * (AST * 2) + c4 * 2);
            *(uint2*)(smem + AH_OFF + off) = hv;
            *(uint2*)(smem + AL_OFF + off) = lv;
        }
        CPA_WAIT0();
        __syncthreads();
    }

    for (int it = 0; it < 16; ++it) {
        uint32_t cb = sb + (uint32_t)((it & 1) * BUF_B);      // compute buffer
        char* np = smem + ((it + 1) & 1) * BUF_B;             // staging buffer
        uint32_t nb = sb + (uint32_t)(((it + 1) & 1) * BUF_B);
        int k0n = (it + 1) * 64;
        bool has_next = (it + 1 < 16);

        // ---- (1) next A chunk -> registers; (2) next Z via cp.async ----
        float4 areg[4];
        if (has_next) {
#pragma unroll
            for (int q = 0; q < 4; q++) {
                int t = tid + 512 * q;
                int r = t >> 4, c4 = (t & 15) * 4;
                areg[q] = *(const float4*)(Ab + (size_t)r * NN + k0n + c4);
            }
#pragma unroll
            for (int q = 0; q < 2; q++) {
                int t = tid + 512 * q;
                int row = t >> 4, g16 = (t & 15) * 16;
                uint32_t off = (uint32_t)(row * (ZST * 2) + g16);
                CPA16(nb + ZH_OFF + off,
                      (const char*)(Zh + (size_t)(k0n + row) * FF) + g16);
                CPA16(nb + ZL_OFF + off,
                      (const char*)(Zl + (size_t)(k0n + row) * FF) + g16);
            }
            CPA_COMMIT();
        }

        // ---- (3) compute current chunk: 4 k16 steps ----
#pragma unroll
        for (int ks = 0; ks < 4; ks++) {
            uint32_t ahi[2][4], alo[2][4], zh[2][4], zl[2][4];
#pragma unroll
            for (int f = 0; f < 2; f++) {
                uint32_t ao = cb + a_loff + (uint32_t)(f * 16 * AST * 2 + ks * 32);
                ldsm4(ahi[f], ao + AH_OFF);
                ldsm4(alo[f], ao + AL_OFF);
            }
#pragma unroll
            for (int jj = 0; jj < 2; jj++) {
                uint32_t bo = cb + b_loff + (uint32_t)(ks * 16 * ZST * 2 + jj * 32);
                ldsm4t(zh[jj], bo + ZH_OFF);
                ldsm4t(zl[jj], bo + ZL_OFF);
            }
#pragma unroll
            for (int f = 0; f < 2; f++)
#pragma unroll
                for (int j = 0; j < 4; j++) {
                    mma16816(acc[f][j], ahi[f], &zh[j >> 1][(j & 1) * 2]);
                    mma16816(acc[f][j], ahi[f], &zl[j >> 1][(j & 1) * 2]);
                    mma16816(acc[f][j], alo[f], &zh[j >> 1][(j & 1) * 2]);
                }
        }

        // ---- (4) convert + STS next A chunk; (5) drain cp.async; sync ----
        if (has_next) {
#pragma unroll
            for (int q = 0; q < 4; q++) {
                int t = tid + 512 * q;
                int r = t >> 4, c4 = (t & 15) * 4;
                float4 v = areg[q];
                __nv_bfloat16 hx = __float2bfloat16(v.x), hy = __float2bfloat16(v.y);
                __nv_bfloat16 hz = __float2bfloat16(v.z), hw = __float2bfloat16(v.w);
                uint2 hv = { pk(hx, hy), pk(hz, hw) };
                uint2 lv = { pk(__float2bfloat16(v.x - __bfloat162float(hx)),
                               __float2bfloat16(v.y - __bfloat162float(hy))),
                             pk(__float2bfloat16(v.z - __bfloat162float(hz)),
                               __float2bfloat16(v.w - __bfloat162float(hw))) };
                uint32_t off = (uint32_t)(r * (AST * 2) + c4 * 2);
                *(uint2*)(np + AH_OFF + off) = hv;
                *(uint2*)(np + AL_OFF + off) = lv;
            }
            CPA_WAIT0();
            __syncthreads();
        }
    }

    // ---- epilogue: acc + Z identity, scale by d_n ----
    int grp = lane >> 2, qid = lane & 3;
#pragma unroll
    for (int f = 0; f < 2; f++) {
        int r0 = m0 + warp_m * 32 + f * 16 + grp;
        int r1 = r0 + 8;
        float d0 = g_dinv[b * NN + r0];
        float d1 = g_dinv[b * NN + r1];
        const float* z0 = g_Zf + ((size_t)b * NN + r0) * FF;
        const float* z1 = g_Zf + ((size_t)b * NN + r1) * FF;
        float* o0 = out + ((size_t)b * NN + r0) * FF;
        float* o1 = out + ((size_t)b * NN + r1) * FF;
#pragma unroll
        for (int j = 0; j < 4; j++) {
            int g = warp_n * 32 + j * 8 + qid * 2;
            float2 za = *(const float2*)(z0 + g);
            float2 zb = *(const float2*)(z1 + g);
            float2 oa, ob;
            oa.x = d0 * (acc[f][j][0] + za.x);
            oa.y = d0 * (acc[f][j][1] + za.y);
            ob.x = d1 * (acc[f][j][2] + zb.x);
            ob.y = d1 * (acc[f][j][3] + zb.y);
            *(float2*)(o0 + g) = oa;
            *(float2*)(o1 + g) = ob;
        }
    }
}

// ---------------------------------------------------------------------------
extern "C" void kernel_launch(void* const* d_in, const int* in_sizes, int n_in,
                              void* d_out, int out_size) {
    const float *X = nullptr, *A = nullptr, *W = nullptr;
    for (int i = 0; i < n_in; i++) {
        if (in_sizes[i] == BATCH * NN * FF)      X = (const float*)d_in[i];
        else if (in_sizes[i] == BATCH * NN * NN) A = (const float*)d_in[i];
        else if (in_sizes[i] == FF * FF)         W = (const float*)d_in[i];
    }
    float* out = (float*)d_out;

    cudaFuncSetAttribute(bmm_mma, cudaFuncAttributeMaxDynamicSharedMemorySize,
                         SMEM_TOTAL);

    deg_kernel<<<(BATCH * NN * 32) / 256, 256>>>(A);
    z_kernel<<<dim3(NN / 128, BATCH), 256>>>(X, W);
    bmm_mma<<<dim3(NN / 128, BATCH), 512, SMEM_TOTAL>>>(A, out);
}